// round 9
// baseline (speedup 1.0000x reference)
#include <cuda_runtime.h>
#include <math.h>

#define BNH 32
#define LL  1024
#define DD  64
#define RR  129
#define TI  16
#define NT  512

#define PSTR 1028
#define KSTR 68
#define VSTR 72
#define GBUF 9216

// shared layout (float units):
//   q_s   [16][68]      @ 0       (1088)
//   av_s  [16][132]     @ 1088    (2112)   qe in phases A/B, av afterwards
//   posi  [16] int      @ 3200
//   posa  [1024] int    @ 3216
//   p_s   [16][1028]    @ 4240    (16448)  scores -> p(tf32) -> PV partials [16][1024]
//   G     2 x 9216      @ 20688   (18432)  cp.async k/v tile ring; upper half: a64[16][132]
//   emb_s [129][68]     @ 39120   (8772)   emb_k in phase A, emb_v afterwards
#define OFF_G 20688
#define SMEM_FLOATS 47892
#define SMEM_BYTES  (SMEM_FLOATS * 4)

#define FIX_SCALE 4503599627370496.0f   /* 2^52 */
#define FIX_INV   (1.0f / 4503599627370496.0f)

__device__ __forceinline__ unsigned tf32b(float x) {
    unsigned u;
    asm("cvt.rna.tf32.f32 %0, %1;" : "=r"(u) : "f"(x));
    return u;
}
__device__ __forceinline__ float tf32r(float x) { return __uint_as_float(tf32b(x)); }

__device__ __forceinline__ void cp16(unsigned saddr, const float* g) {
    asm volatile("cp.async.ca.shared.global [%0], [%1], 16;" :: "r"(saddr), "l"(g));
}
#define CP_COMMIT() asm volatile("cp.async.commit_group;")
#define CP_WAIT0()  asm volatile("cp.async.wait_group 0;")

#define MMA_TF32(c0,c1,c2,c3,a0,a1,a2,a3,b0,b1)                               \
    asm volatile("mma.sync.aligned.m16n8k8.row.col.f32.tf32.tf32.f32 "        \
                 "{%0,%1,%2,%3}, {%4,%5,%6,%7}, {%8,%9}, {%0,%1,%2,%3};"      \
                 : "+f"(c0), "+f"(c1), "+f"(c2), "+f"(c3)                      \
                 : "r"(a0), "r"(a1), "r"(a2), "r"(a3), "r"(b0), "r"(b1))

// issue one 128x64 fp32 tile (2048 x 16B) global -> shared, stride in floats
__device__ __forceinline__ void issue_tile(unsigned sbase, const float* gsrc,
                                           int tid, int stride) {
    #pragma unroll
    for (int s = 0; s < 4; s++) {
        int f = tid + s * NT;
        int row = f >> 4, c4 = f & 15;
        cp16(sbase + (unsigned)(row * stride + c4 * 4) * 4u, gsrc + row * 64 + c4 * 4);
    }
}

extern "C" __global__ void __launch_bounds__(NT, 1)
attn_rel_kernel(const float* __restrict__ gq, const float* __restrict__ gk,
                const float* __restrict__ gv, const float* __restrict__ gw,
                const float* __restrict__ gek, const float* __restrict__ gev,
                const int* __restrict__ gpos, const unsigned char* __restrict__ gmask,
                float* __restrict__ gout, float* __restrict__ gp)
{
    extern __shared__ float sm[];
    float* q_s   = sm;
    float* av_s  = sm + 1088;
    int*   posi  = (int*)(sm + 3200);
    int*   posa  = (int*)(sm + 3216);
    float* p_s   = sm + 4240;
    float* G     = sm + OFF_G;
    float* emb_s = sm + 39120;
    const unsigned Gu = (unsigned)__cvta_generic_to_shared(sm) + OFF_G * 4u;

    const int b    = blockIdx.y;
    const int i0   = blockIdx.x * TI;
    const int tid  = threadIdx.x;
    const int lane = tid & 31;
    const int warp = tid >> 5;          // 0..15
    const unsigned FULL = 0xffffffffu;

    const int gid  = lane >> 2;         // 0..7
    const int tid4 = lane & 3;          // 0..3

    // ---------------- loads: q tile, pos, emb_k ----------------
    {
        if (tid < 256) {
            const float4* q4 = (const float4*)(gq + ((size_t)b * LL + i0) * DD);
            int row = tid >> 4, c4 = tid & 15;
            *(float4*)(q_s + row * 68 + c4 * 4) = q4[tid];
        }
        if (tid < TI) posi[tid] = gpos[b * LL + i0 + tid];
        #pragma unroll
        for (int t = tid; t < LL; t += NT) posa[t] = gpos[b * LL + t];
        for (int e = tid; e < RR * DD; e += NT) {
            int r = e >> 6, d = e & 63;
            emb_s[r * 68 + d] = gek[e];
        }
    }
    __syncthreads();

    // ---------------- phase A: qe[i][r] = q[i] . emb_k[r]  (exact fp32) ----------------
    for (int e = tid; e < TI * RR; e += NT) {
        int i = e / RR, r = e - i * RR;
        const float4* qa = (const float4*)(q_s + i * 68);
        const float4* ea = (const float4*)(emb_s + r * 68);
        float acc = 0.f;
        #pragma unroll
        for (int c = 0; c < 16; c++) {
            float4 a = qa[c], e2 = ea[c];
            acc += a.x*e2.x + a.y*e2.y + a.z*e2.z + a.w*e2.w;
        }
        av_s[i * 132 + r] = acc;
    }

    // persistent tf32 A-fragments of q (rna-rounded)
    unsigned af[8][4];
    #pragma unroll
    for (int ks = 0; ks < 8; ks++) {
        af[ks][0] = tf32b(q_s[ gid      * 68 + ks * 8 + tid4    ]);
        af[ks][1] = tf32b(q_s[(gid + 8) * 68 + ks * 8 + tid4    ]);
        af[ks][2] = tf32b(q_s[ gid      * 68 + ks * 8 + tid4 + 4]);
        af[ks][3] = tf32b(q_s[(gid + 8) * 68 + ks * 8 + tid4 + 4]);
    }
    __syncthreads();     // phase A done (emb_k free), af built

    // prologue: k tile 0 via cp.async; emb_v overwrite of emb_s overlaps it
    issue_tile(Gu, gk + (size_t)b * LL * DD, tid, KSTR);
    CP_COMMIT();
    for (int e = tid; e < RR * DD; e += NT) {
        int r = e >> 6, d = e & 63;
        emb_s[r * 68 + d] = gev[e];
    }

    // ---------------- phase B: scores = (QK^T + qe[table] + attn_w)/8, mask ----------------
    const int jbase = warp * 8;         // 8 j columns per warp per 128-tile
    const int i_lo = gid, i_hi = gid + 8;
    const int pi_lo = posi[i_lo], pi_hi = posi[i_hi];
    const size_t row_lo = ((size_t)b * LL + (i0 + i_lo)) * LL;
    const size_t row_hi = ((size_t)b * LL + (i0 + i_hi)) * LL;

    for (int jt = 0; jt < 8; jt++) {
        // prefetch attn_w / mask for the epilogue (DRAM latency behind wait+mma)
        const int jg0 = jt * 128 + jbase + tid4 * 2;
        float2 w_lo = *(const float2*)(gw + row_lo + jg0);
        float2 w_hi = *(const float2*)(gw + row_hi + jg0);
        uchar2 m_lo = *(const uchar2*)(gmask + row_lo + jg0);
        uchar2 m_hi = *(const uchar2*)(gmask + row_hi + jg0);

        CP_WAIT0();                 // my chunks of tile jt done
        __syncthreads();            // everyone's chunks done + buf (jt+1)&1 consumed
        if (jt < 7) {
            issue_tile(Gu + ((jt + 1) & 1) * GBUF * 4u,
                       gk + ((size_t)b * LL + (jt + 1) * 128) * DD, tid, KSTR);
            CP_COMMIT();
        }
        const float* Gc = G + (jt & 1) * GBUF;

        float c0 = 0.f, c1 = 0.f, c2 = 0.f, c3 = 0.f;
        #pragma unroll
        for (int ks = 0; ks < 8; ks++) {
            const float* kb = Gc + (jbase + gid) * KSTR + ks * 8 + tid4;
            unsigned b0 = __float_as_uint(kb[0]);
            unsigned b1 = __float_as_uint(kb[4]);
            MMA_TF32(c0, c1, c2, c3,
                     af[ks][0], af[ks][1], af[ks][2], af[ks][3], b0, b1);
        }

        // epilogue: rel-pos gather + attn_w, scale, mask, store to p_s
        {
            int pj0 = posa[jg0], pj1 = posa[jg0 + 1];
            int d00 = max(-64, min(64, pj0 - pi_lo)) + 64;
            int d01 = max(-64, min(64, pj1 - pi_lo)) + 64;
            int d10 = max(-64, min(64, pj0 - pi_hi)) + 64;
            int d11 = max(-64, min(64, pj1 - pi_hi)) + 64;
            float s00 = (c0 + av_s[i_lo * 132 + d00] + w_lo.x) * 0.125f;
            float s01 = (c1 + av_s[i_lo * 132 + d01] + w_lo.y) * 0.125f;
            float s10 = (c2 + av_s[i_hi * 132 + d10] + w_hi.x) * 0.125f;
            float s11 = (c3 + av_s[i_hi * 132 + d11] + w_hi.y) * 0.125f;
            if (m_lo.x) s00 = -INFINITY;
            if (m_lo.y) s01 = -INFINITY;
            if (m_hi.x) s10 = -INFINITY;
            if (m_hi.y) s11 = -INFINITY;
            *(float2*)(p_s + i_lo * PSTR + jg0) = make_float2(s00, s01);
            *(float2*)(p_s + i_hi * PSTR + jg0) = make_float2(s10, s11);
        }
    }
    __syncthreads();                // all of p_s written; G fully consumed

    // prefetch v tile 0 into buf0 — overlaps phase C (a64 lives in buf1)
    issue_tile(Gu, gv + (size_t)b * LL * DD, tid, VSTR);
    CP_COMMIT();

    // ---------------- phase C: softmax + p write + av scatter (register-resident) ----------------
    {
        const int i = warp;                     // 16 warps, one row each
        float* row = p_s + i * PSTR;
        float r[32];
        #pragma unroll
        for (int c = 0; c < 32; c++) r[c] = row[lane + 32*c];

        float m = -INFINITY;
        #pragma unroll
        for (int c = 0; c < 32; c++) m = fmaxf(m, r[c]);
        #pragma unroll
        for (int o = 16; o > 0; o >>= 1) m = fmaxf(m, __shfl_xor_sync(FULL, m, o));

        float sum = 0.f;
        #pragma unroll
        for (int c = 0; c < 32; c++) {
            r[c] = __expf(r[c] - m);
            sum += r[c];
        }
        #pragma unroll
        for (int o = 16; o > 0; o >>= 1) sum += __shfl_xor_sync(FULL, sum, o);
        float inv = 1.0f / sum;

        // fixed-point scatter into 129 buckets (exact integer adds -> deterministic)
        unsigned long long* a64 = (unsigned long long*)(G + GBUF) + (size_t)i * 132;
        #pragma unroll
        for (int c = 0; c < 5; c++) {
            int idx = lane + 32*c;
            if (idx < 132) a64[idx] = 0ull;
        }
        __syncwarp();

        const int pi = posi[i];
        const size_t prow = ((size_t)b * LL + (i0 + i)) * LL;
        #pragma unroll
        for (int c = 0; c < 32; c++) {
            int j = lane + 32*c;
            float pv = r[c] * inv;
            if (gp) gp[prow + j] = pv;
            int diff = posa[j] - pi;
            diff = max(-64, min(64, diff));
            atomicAdd(a64 + diff + 64, (unsigned long long)(pv * FIX_SCALE));
            row[j] = tf32r(pv);         // tf32 p for P@V (gp holds exact p)
        }
        __syncwarp();

        #pragma unroll
        for (int c = 0; c < 5; c++) {
            int idx = lane + 32*c;
            if (idx < RR)
                av_s[i * 132 + idx] = __ull2float_rn(a64[idx]) * FIX_INV;
        }
    }
    __syncthreads();                // phase C done (a64 reads finished)

    // ---------------- phase D: out = P @ V  (warp = ks-group, A-frag reuse x8) ----------------
    float cd[8][4];
    #pragma unroll
    for (int dt = 0; dt < 8; dt++)
        #pragma unroll
        for (int x = 0; x < 4; x++) cd[dt][x] = 0.f;

    for (int jt = 0; jt < 8; jt++) {
        CP_WAIT0();
        __syncthreads();
        if (jt < 7) {
            issue_tile(Gu + ((jt + 1) & 1) * GBUF * 4u,
                       gv + ((size_t)b * LL + (jt + 1) * 128) * DD, tid, VSTR);
            CP_COMMIT();
        }
        const float* Gc = G + (jt & 1) * GBUF;

        const int jcol = jt * 128 + warp * 8 + tid4;
        unsigned a0 = __float_as_uint(p_s[ gid      * PSTR + jcol    ]);
        unsigned a1 = __float_as_uint(p_s[(gid + 8) * PSTR + jcol    ]);
        unsigned a2 = __float_as_uint(p_s[ gid      * PSTR + jcol + 4]);
        unsigned a3 = __float_as_uint(p_s[(gid + 8) * PSTR + jcol + 4]);

        #pragma unroll
        for (int dt = 0; dt < 8; dt++) {
            const float* vb = Gc + (warp * 8 + tid4) * VSTR + dt * 8 + gid;
            unsigned b0 = __float_as_uint(vb[0]);
            unsigned b1 = __float_as_uint(vb[4 * VSTR]);
            MMA_TF32(cd[dt][0], cd[dt][1], cd[dt][2], cd[dt][3],
                     a0, a1, a2, a3, b0, b1);
        }
    }
    __syncthreads();                // all p_s A-frag reads done -> p_s reusable

    // store per-warp PV partials into p_s (flat [16][16][64])
    {
        float* P = p_s + warp * 1024;
        #pragma unroll
        for (int dt = 0; dt < 8; dt++) {
            int d0 = dt * 8 + tid4 * 2;
            *(float2*)(P +  gid      * 64 + d0) = make_float2(cd[dt][0], cd[dt][1]);
            *(float2*)(P + (gid + 8) * 64 + d0) = make_float2(cd[dt][2], cd[dt][3]);
        }
    }
    __syncthreads();

    // ---------------- final: out = sum of 16 partials + av @ emb_v (exact fp32) ----------------
    if (gout) {
        int o2 = tid * 2;               // 0..1022
        int i = o2 >> 6, d = o2 & 63;
        float sx = 0.f, sy = 0.f;
        #pragma unroll
        for (int w = 0; w < 16; w++) {
            float2 t = *(const float2*)(p_s + w * 1024 + o2);
            sx += t.x; sy += t.y;
        }
        const float* avr = av_s + i * 132;
        #pragma unroll 8
        for (int r = 0; r < RR; r++) {
            float a = avr[r];
            float2 e = *(const float2*)(emb_s + r * 68 + d);
            sx += a * e.x; sy += a * e.y;
        }
        *(float2*)(gout + ((size_t)b * LL + i0 + i) * DD + o2 % 64 + (size_t)0) = make_float2(sx, sy);
        // note: o2 % 64 == d
    }
}

extern "C" void kernel_launch(void* const* d_in, const int* in_sizes, int n_in,
                              void* d_out, int out_size)
{
    const float* q   = (const float*)d_in[0];
    const float* k   = (const float*)d_in[1];
    const float* v   = (const float*)d_in[2];
    const float* w   = (const float*)d_in[3];
    const float* ek  = (const float*)d_in[4];
    const float* ev  = (const float*)d_in[5];
    const int*   pos = (const int*)d_in[6];
    const unsigned char* mask = (const unsigned char*)d_in[7];

    const long OUT_N = (long)BNH * LL * DD;   // 2,097,152
    const long P_N   = (long)BNH * LL * LL;   // 33,554,432

    float* outp = nullptr;
    float* pp   = nullptr;
    if ((long)out_size == OUT_N) {
        outp = (float*)d_out;
    } else if ((long)out_size == P_N) {
        pp = (float*)d_out;
    } else {
        outp = (float*)d_out;
        pp   = (float*)d_out + OUT_N;
    }

    cudaFuncSetAttribute(attn_rel_kernel,
                         cudaFuncAttributeMaxDynamicSharedMemorySize, SMEM_BYTES);
    dim3 grid(LL / TI, BNH);
    attn_rel_kernel<<<grid, NT, SMEM_BYTES>>>(q, k, v, w, ek, ev, pos, mask, outp, pp);
}

// round 10
// speedup vs baseline: 1.5037x; 1.5037x over previous
#include <cuda_runtime.h>
#include <math.h>

#define BNH 32
#define LL  1024
#define DD  64
#define RR  129
#define TI  16
#define NT  512

#define AVSTR 136
#define PSTR  1028
#define KSTR  68
#define VSTR  72
#define ESTR  68      // emb_k stride
#define EVSTR 72      // emb_v stride
#define PPART 1152    // partial-buffer stride per warp (16 rows x 72)

// shared layout (float units):
//   q_s   [16][68]      @ 0       (1088)
//   av_s  [16][136]     @ 1088    (2176)   qe (mma) -> av; cols 129..135 stay 0
//   posi  [16] int      @ 3264
//   posa  [1024] int    @ 3280
//   p_s   [16][1028]    @ 4304    (16448)  scores -> p(tf32); then (with G) PV partials [16][1152]
//   G     [9216]        @ 20752   k-tiles[128][68] / a64[16][264] / v-tiles[128][72] / partial tail
//   emb   [136][72]     @ 29968   emb_k (stride 68, phase A) -> emb_v (stride 72)
#define OFF_Q    0
#define OFF_AV   1088
#define OFF_POSI 3264
#define OFF_POSA 3280
#define OFF_P    4304
#define OFF_G    20752
#define OFF_E    29968
#define SMEM_FLOATS 39760
#define SMEM_BYTES  (SMEM_FLOATS * 4)

#define FIX_SCALE 4503599627370496.0f   /* 2^52 */
#define FIX_INV   (1.0f / 4503599627370496.0f)

__device__ __forceinline__ unsigned tf32b(float x) {
    unsigned u;
    asm("cvt.rna.tf32.f32 %0, %1;" : "=r"(u) : "f"(x));
    return u;
}
__device__ __forceinline__ float tf32r(float x) { return __uint_as_float(tf32b(x)); }
__device__ __forceinline__ float4 tf32r4(float4 a) {
    a.x = tf32r(a.x); a.y = tf32r(a.y); a.z = tf32r(a.z); a.w = tf32r(a.w);
    return a;
}

#define MMA_TF32(c0,c1,c2,c3,a0,a1,a2,a3,b0,b1)                               \
    asm volatile("mma.sync.aligned.m16n8k8.row.col.f32.tf32.tf32.f32 "        \
                 "{%0,%1,%2,%3}, {%4,%5,%6,%7}, {%8,%9}, {%0,%1,%2,%3};"      \
                 : "+f"(c0), "+f"(c1), "+f"(c2), "+f"(c3)                      \
                 : "r"(a0), "r"(a1), "r"(a2), "r"(a3), "r"(b0), "r"(b1))

extern "C" __global__ void __launch_bounds__(NT, 1)
attn_rel_kernel(const float* __restrict__ gq, const float* __restrict__ gk,
                const float* __restrict__ gv, const float* __restrict__ gw,
                const float* __restrict__ gek, const float* __restrict__ gev,
                const int* __restrict__ gpos, const unsigned char* __restrict__ gmask,
                float* __restrict__ gout, float* __restrict__ gp)
{
    extern __shared__ float sm[];
    float* q_s  = sm + OFF_Q;
    float* av_s = sm + OFF_AV;
    int*   posi = (int*)(sm + OFF_POSI);
    int*   posa = (int*)(sm + OFF_POSA);
    float* p_s  = sm + OFF_P;
    float* G    = sm + OFF_G;
    float* e_s  = sm + OFF_E;

    const int b    = blockIdx.y;
    const int i0   = blockIdx.x * TI;
    const int tid  = threadIdx.x;
    const int lane = tid & 31;
    const int warp = tid >> 5;          // 0..15
    const unsigned FULL = 0xffffffffu;

    const int gid  = lane >> 2;         // 0..7
    const int tid4 = lane & 3;          // 0..3

    // ---------------- loads: q tile, pos, emb_k (tf32, padded to 136 rows) ----------------
    {
        if (tid < 256) {
            const float4* q4 = (const float4*)(gq + ((size_t)b * LL + i0) * DD);
            int row = tid >> 4, c4 = tid & 15;
            *(float4*)(q_s + row * 68 + c4 * 4) = q4[tid];
        }
        if (tid < TI) posi[tid] = gpos[b * LL + i0 + tid];
        #pragma unroll
        for (int t = tid; t < LL; t += NT) posa[t] = gpos[b * LL + t];
        for (int e = tid; e < 136 * 64; e += NT) {
            int r = e >> 6, d = e & 63;
            e_s[r * ESTR + d] = (r < RR) ? tf32r(gek[r * 64 + d]) : 0.f;
        }
    }
    __syncthreads();

    // persistent tf32 A-fragments of q (rna)
    unsigned af[8][4];
    #pragma unroll
    for (int ks = 0; ks < 8; ks++) {
        af[ks][0] = tf32b(q_s[ gid      * 68 + ks * 8 + tid4    ]);
        af[ks][1] = tf32b(q_s[(gid + 8) * 68 + ks * 8 + tid4    ]);
        af[ks][2] = tf32b(q_s[ gid      * 68 + ks * 8 + tid4 + 4]);
        af[ks][3] = tf32b(q_s[(gid + 8) * 68 + ks * 8 + tid4 + 4]);
    }

    // ---------------- phase A: qe[i][r] = q[i] . emb_k[r] via tf32 mma ----------------
    for (int t = warp; t < 17; t += 16) {       // warp 0 also does tile 16
        float c0 = 0.f, c1 = 0.f, c2 = 0.f, c3 = 0.f;
        #pragma unroll
        for (int ks = 0; ks < 8; ks++) {
            const float* kb = e_s + (t * 8 + gid) * ESTR + ks * 8 + tid4;
            unsigned b0 = __float_as_uint(kb[0]);
            unsigned b1 = __float_as_uint(kb[4]);
            MMA_TF32(c0, c1, c2, c3,
                     af[ks][0], af[ks][1], af[ks][2], af[ks][3], b0, b1);
        }
        int r0 = t * 8 + tid4 * 2;
        av_s[ gid      * AVSTR + r0    ] = c0;
        av_s[ gid      * AVSTR + r0 + 1] = c1;
        av_s[(gid + 8) * AVSTR + r0    ] = c2;
        av_s[(gid + 8) * AVSTR + r0 + 1] = c3;
    }
    __syncthreads();        // qe ready; emb_k region free

    // overwrite emb region with emb_v (tf32, stride 72, padded rows zeroed)
    for (int e = tid; e < 136 * 64; e += NT) {
        int r = e >> 6, d = e & 63;
        e_s[r * EVSTR + d] = (r < RR) ? tf32r(gev[r * 64 + d]) : 0.f;
    }

    // ---------------- phase B: scores = (QK^T + qe[table] + attn_w)/8, mask ----------------
    const int jbase = warp * 8;
    const int i_lo = gid, i_hi = gid + 8;
    const int pi_lo = posi[i_lo], pi_hi = posi[i_hi];
    const size_t row_lo = ((size_t)b * LL + (i0 + i_lo)) * LL;
    const size_t row_hi = ((size_t)b * LL + (i0 + i_hi)) * LL;

    for (int jt = 0; jt < 8; jt++) {
        {   // k tile jt -> G (tf32 rna, stride 68)
            const float4* k4 = (const float4*)(gk + ((size_t)b * LL + jt * 128) * DD);
            #pragma unroll
            for (int s = 0; s < 4; s++) {
                int f = tid + s * NT;
                int row = f >> 4, c4 = f & 15;
                *(float4*)(G + row * KSTR + c4 * 4) = tf32r4(k4[f]);
            }
        }
        // prefetch attn_w / mask (DRAM latency behind STS+sync+mma)
        const int jg0 = jt * 128 + jbase + tid4 * 2;
        float2 w_lo = *(const float2*)(gw + row_lo + jg0);
        float2 w_hi = *(const float2*)(gw + row_hi + jg0);
        uchar2 m_lo = *(const uchar2*)(gmask + row_lo + jg0);
        uchar2 m_hi = *(const uchar2*)(gmask + row_hi + jg0);
        __syncthreads();

        float c0 = 0.f, c1 = 0.f, c2 = 0.f, c3 = 0.f;
        #pragma unroll
        for (int ks = 0; ks < 8; ks++) {
            const float* kb = G + (jbase + gid) * KSTR + ks * 8 + tid4;
            unsigned b0 = __float_as_uint(kb[0]);
            unsigned b1 = __float_as_uint(kb[4]);
            MMA_TF32(c0, c1, c2, c3,
                     af[ks][0], af[ks][1], af[ks][2], af[ks][3], b0, b1);
        }

        {   // epilogue: rel-pos gather + attn_w, scale, mask, store to p_s
            int pj0 = posa[jg0], pj1 = posa[jg0 + 1];
            int d00 = max(-64, min(64, pj0 - pi_lo)) + 64;
            int d01 = max(-64, min(64, pj1 - pi_lo)) + 64;
            int d10 = max(-64, min(64, pj0 - pi_hi)) + 64;
            int d11 = max(-64, min(64, pj1 - pi_hi)) + 64;
            float s00 = (c0 + av_s[i_lo * AVSTR + d00] + w_lo.x) * 0.125f;
            float s01 = (c1 + av_s[i_lo * AVSTR + d01] + w_lo.y) * 0.125f;
            float s10 = (c2 + av_s[i_hi * AVSTR + d10] + w_hi.x) * 0.125f;
            float s11 = (c3 + av_s[i_hi * AVSTR + d11] + w_hi.y) * 0.125f;
            if (m_lo.x) s00 = -INFINITY;
            if (m_lo.y) s01 = -INFINITY;
            if (m_hi.x) s10 = -INFINITY;
            if (m_hi.y) s11 = -INFINITY;
            *(float2*)(p_s + i_lo * PSTR + jg0) = make_float2(s00, s01);
            *(float2*)(p_s + i_hi * PSTR + jg0) = make_float2(s10, s11);
        }
        __syncthreads();
    }

    // ---------------- phase C: softmax + p write + av scatter (register-resident) ----------------
    {
        const int i = warp;
        float* row = p_s + i * PSTR;
        float r[32];
        #pragma unroll
        for (int c = 0; c < 32; c++) r[c] = row[lane + 32*c];

        float m = -INFINITY;
        #pragma unroll
        for (int c = 0; c < 32; c++) m = fmaxf(m, r[c]);
        #pragma unroll
        for (int o = 16; o > 0; o >>= 1) m = fmaxf(m, __shfl_xor_sync(FULL, m, o));

        float sum = 0.f;
        #pragma unroll
        for (int c = 0; c < 32; c++) {
            r[c] = __expf(r[c] - m);
            sum += r[c];
        }
        #pragma unroll
        for (int o = 16; o > 0; o >>= 1) sum += __shfl_xor_sync(FULL, sum, o);
        float inv = 1.0f / sum;

        // fixed-point scatter into 129 buckets, 2 banks (exact -> deterministic)
        unsigned long long* a64 = (unsigned long long*)G + (size_t)i * 264;
        #pragma unroll
        for (int c = 0; c < 9; c++) {
            int idx = lane + 32*c;
            if (idx < 264) a64[idx] = 0ull;
        }
        __syncwarp();

        const int pi = posi[i];
        const int bank = lane & 1;
        const size_t prow = ((size_t)b * LL + (i0 + i)) * LL;
        #pragma unroll
        for (int c = 0; c < 32; c++) {
            int j = lane + 32*c;
            float pv = r[c] * inv;
            if (gp) gp[prow + j] = pv;
            int diff = posa[j] - pi;
            diff = max(-64, min(64, diff));
            atomicAdd(a64 + (diff + 64) * 2 + bank,
                      (unsigned long long)(pv * FIX_SCALE));
            row[j] = tf32r(pv);         // tf32 p for P@V (gp holds exact p)
        }
        __syncwarp();

        #pragma unroll
        for (int c = 0; c < 5; c++) {
            int idx = lane + 32*c;
            if (idx < RR)
                av_s[i * AVSTR + idx] =
                    __ull2float_rn(a64[idx*2] + a64[idx*2+1]) * FIX_INV;
        }
    }
    __syncthreads();        // av ready; a64 (G) free

    // ---------------- av @ emb_v via tf32 mma (k split over warps) -> seeds cd ----------------
    float cd[8][4];
    #pragma unroll
    for (int dt = 0; dt < 8; dt++)
        #pragma unroll
        for (int x = 0; x < 4; x++) cd[dt][x] = 0.f;

    for (int ks = warp; ks < 17; ks += 16) {    // warp 0 also does ks=16
        int k0 = ks * 8 + tid4;
        unsigned a0 = __float_as_uint(av_s[ gid      * AVSTR + k0    ]);
        unsigned a1 = __float_as_uint(av_s[(gid + 8) * AVSTR + k0    ]);
        unsigned a2 = __float_as_uint(av_s[ gid      * AVSTR + k0 + 4]);
        unsigned a3 = __float_as_uint(av_s[(gid + 8) * AVSTR + k0 + 4]);
        #pragma unroll
        for (int dt = 0; dt < 8; dt++) {
            unsigned b0 = __float_as_uint(e_s[ k0      * EVSTR + dt * 8 + gid]);
            unsigned b1 = __float_as_uint(e_s[(k0 + 4) * EVSTR + dt * 8 + gid]);
            MMA_TF32(cd[dt][0], cd[dt][1], cd[dt][2], cd[dt][3],
                     a0, a1, a2, a3, b0, b1);
        }
    }

    // ---------------- phase D: out += P @ V  (warp = j-slice, A-frag reuse x8) ----------------
    for (int jt = 0; jt < 8; jt++) {
        __syncthreads();    // G free (a64 done / prev tile's mma done)
        {   // v tile jt -> G (tf32 rna, stride 72)
            const float4* v4 = (const float4*)(gv + ((size_t)b * LL + jt * 128) * DD);
            #pragma unroll
            for (int s = 0; s < 4; s++) {
                int f = tid + s * NT;
                int row = f >> 4, c4 = f & 15;
                *(float4*)(G + row * VSTR + c4 * 4) = tf32r4(v4[f]);
            }
        }
        __syncthreads();

        const int jcol = jt * 128 + warp * 8 + tid4;
        unsigned a0 = __float_as_uint(p_s[ gid      * PSTR + jcol    ]);
        unsigned a1 = __float_as_uint(p_s[(gid + 8) * PSTR + jcol    ]);
        unsigned a2 = __float_as_uint(p_s[ gid      * PSTR + jcol + 4]);
        unsigned a3 = __float_as_uint(p_s[(gid + 8) * PSTR + jcol + 4]);

        #pragma unroll
        for (int dt = 0; dt < 8; dt++) {
            const float* vb = G + (warp * 8 + tid4) * VSTR + dt * 8 + gid;
            unsigned b0 = __float_as_uint(vb[0]);
            unsigned b1 = __float_as_uint(vb[4 * VSTR]);
            MMA_TF32(cd[dt][0], cd[dt][1], cd[dt][2], cd[dt][3],
                     a0, a1, a2, a3, b0, b1);
        }
    }
    __syncthreads();        // all p_s A-frag reads done -> p_s/G reusable

    // store per-warp partials [16][16 x 72] into p_s..G area (bank-clean stride 72)
    {
        float* P = p_s + warp * PPART;
        #pragma unroll
        for (int dt = 0; dt < 8; dt++) {
            int d0 = dt * 8 + tid4 * 2;
            *(float2*)(P +  gid      * 72 + d0) = make_float2(cd[dt][0], cd[dt][1]);
            *(float2*)(P + (gid + 8) * 72 + d0) = make_float2(cd[dt][2], cd[dt][3]);
        }
    }
    __syncthreads();

    // ---------------- final: out = sum of 16 partials (av@emb_v already included) ----------------
    if (gout) {
        int o2 = tid * 2;               // 0..1022
        int i = o2 >> 6, d = o2 & 63;
        float sx = 0.f, sy = 0.f;
        #pragma unroll
        for (int w = 0; w < 16; w++) {
            float2 t = *(const float2*)(p_s + w * PPART + i * 72 + d);
            sx += t.x; sy += t.y;
        }
        *(float2*)(gout + ((size_t)b * LL + i0 + i) * DD + d) = make_float2(sx, sy);
    }
}

extern "C" void kernel_launch(void* const* d_in, const int* in_sizes, int n_in,
                              void* d_out, int out_size)
{
    const float* q   = (const float*)d_in[0];
    const float* k   = (const float*)d_in[1];
    const float* v   = (const float*)d_in[2];
    const float* w   = (const float*)d_in[3];
    const float* ek  = (const float*)d_in[4];
    const float* ev  = (const float*)d_in[5];
    const int*   pos = (const int*)d_in[6];
    const unsigned char* mask = (const unsigned char*)d_in[7];

    const long OUT_N = (long)BNH * LL * DD;   // 2,097,152
    const long P_N   = (long)BNH * LL * LL;   // 33,554,432

    float* outp = nullptr;
    float* pp   = nullptr;
    if ((long)out_size == OUT_N) {
        outp = (float*)d_out;
    } else if ((long)out_size == P_N) {
        pp = (float*)d_out;
    } else {
        outp = (float*)d_out;
        pp   = (float*)d_out + OUT_N;
    }

    cudaFuncSetAttribute(attn_rel_kernel,
                         cudaFuncAttributeMaxDynamicSharedMemorySize, SMEM_BYTES);
    dim3 grid(LL / TI, BNH);
    attn_rel_kernel<<<grid, NT, SMEM_BYTES>>>(q, k, v, w, ek, ev, pos, mask, outp, pp);
}

// round 11
// speedup vs baseline: 1.7261x; 1.1479x over previous
#include <cuda_runtime.h>
#include <math.h>

#define BNH 32
#define LL  1024
#define DD  64
#define RR  129
#define TI  16
#define TJ  256
#define NT  512

#define AVSTR 136
#define PSTR  1028
#define KSTR  68
#define ESTR  68
#define AVG   192      // av scratch stride (cols 129..191 zero)

// ---------------- K1 shared layout (float units) ----------------
//   q_s   [16][68]   @ 0      (1088)
//   av_s  [16][136]  @ 1088   (2176)  qe for phase B gather
//   posi  [16]       @ 3264
//   posa  [1024]     @ 3280
//   p_s   [16][1028] @ 4304   (16448) scores
//   G     [17408]    @ 20752  emb_k[136][68] -> k-tiles[256][68] -> a64[16][264]
#define OFF_Q    0
#define OFF_AV   1088
#define OFF_POSI 3264
#define OFF_POSA 3280
#define OFF_P    4304
#define OFF_G    20752
#define K1_FLOATS 38160
#define K1_BYTES  (K1_FLOATS * 4)

#define FIX_SCALE 4503599627370496.0f   /* 2^52 */
#define FIX_INV   (1.0f / 4503599627370496.0f)

__device__ float g_av[(size_t)BNH * LL * AVG];        // 25 MB scratch
__device__ float g_p_scratch[(size_t)BNH * LL * LL];  // used only if gp is null

__device__ __forceinline__ unsigned tf32b(float x) {
    unsigned u;
    asm("cvt.rna.tf32.f32 %0, %1;" : "=r"(u) : "f"(x));
    return u;
}
__device__ __forceinline__ float tf32r(float x) { return __uint_as_float(tf32b(x)); }
__device__ __forceinline__ float4 tf32r4(float4 a) {
    a.x = tf32r(a.x); a.y = tf32r(a.y); a.z = tf32r(a.z); a.w = tf32r(a.w);
    return a;
}

#define MMA_TF32(c0,c1,c2,c3,a0,a1,a2,a3,b0,b1)                               \
    asm volatile("mma.sync.aligned.m16n8k8.row.col.f32.tf32.tf32.f32 "        \
                 "{%0,%1,%2,%3}, {%4,%5,%6,%7}, {%8,%9}, {%0,%1,%2,%3};"      \
                 : "+f"(c0), "+f"(c1), "+f"(c2), "+f"(c3)                      \
                 : "r"(a0), "r"(a1), "r"(a2), "r"(a3), "r"(b0), "r"(b1))

// ===================== K1: scores + softmax + p + av =====================
extern "C" __global__ void __launch_bounds__(NT, 1)
attn_scores_kernel(const float* __restrict__ gq, const float* __restrict__ gk,
                   const float* __restrict__ gw, const float* __restrict__ gek,
                   const int* __restrict__ gpos, const unsigned char* __restrict__ gmask,
                   float* __restrict__ gp)
{
    extern __shared__ float sm[];
    float* q_s  = sm + OFF_Q;
    float* av_s = sm + OFF_AV;
    int*   posi = (int*)(sm + OFF_POSI);
    int*   posa = (int*)(sm + OFF_POSA);
    float* p_s  = sm + OFF_P;
    float* G    = sm + OFF_G;

    const int b    = blockIdx.y;
    const int i0   = blockIdx.x * TI;
    const int tid  = threadIdx.x;
    const int lane = tid & 31;
    const int warp = tid >> 5;          // 0..15
    const unsigned FULL = 0xffffffffu;

    const int gid  = lane >> 2;
    const int tid4 = lane & 3;

    float* pdst = gp ? gp : g_p_scratch;

    // ---------------- loads: q, pos, emb_k (tf32, 136 rows padded) into G ----------------
    {
        if (tid < 256) {
            const float4* q4 = (const float4*)(gq + ((size_t)b * LL + i0) * DD);
            int row = tid >> 4, c4 = tid & 15;
            *(float4*)(q_s + row * 68 + c4 * 4) = q4[tid];
        }
        if (tid < TI) posi[tid] = gpos[b * LL + i0 + tid];
        #pragma unroll
        for (int t = tid; t < LL; t += NT) posa[t] = gpos[b * LL + t];
        for (int e = tid; e < 136 * 64; e += NT) {
            int r = e >> 6, d = e & 63;
            G[r * ESTR + d] = (r < RR) ? tf32r(gek[r * 64 + d]) : 0.f;
        }
    }
    __syncthreads();

    // persistent tf32 A-fragments of q (rna)
    unsigned af[8][4];
    #pragma unroll
    for (int ks = 0; ks < 8; ks++) {
        af[ks][0] = tf32b(q_s[ gid      * 68 + ks * 8 + tid4    ]);
        af[ks][1] = tf32b(q_s[(gid + 8) * 68 + ks * 8 + tid4    ]);
        af[ks][2] = tf32b(q_s[ gid      * 68 + ks * 8 + tid4 + 4]);
        af[ks][3] = tf32b(q_s[(gid + 8) * 68 + ks * 8 + tid4 + 4]);
    }

    // ---------------- phase A: qe = q . emb_k^T via tf32 mma ----------------
    for (int t = warp; t < 17; t += 16) {       // warp 0 also does tile 16
        float c0 = 0.f, c1 = 0.f, c2 = 0.f, c3 = 0.f;
        #pragma unroll
        for (int ks = 0; ks < 8; ks++) {
            const float* kb = G + (t * 8 + gid) * ESTR + ks * 8 + tid4;
            unsigned b0 = __float_as_uint(kb[0]);
            unsigned b1 = __float_as_uint(kb[4]);
            MMA_TF32(c0, c1, c2, c3,
                     af[ks][0], af[ks][1], af[ks][2], af[ks][3], b0, b1);
        }
        int r0 = t * 8 + tid4 * 2;
        av_s[ gid      * AVSTR + r0    ] = c0;
        av_s[ gid      * AVSTR + r0 + 1] = c1;
        av_s[(gid + 8) * AVSTR + r0    ] = c2;
        av_s[(gid + 8) * AVSTR + r0 + 1] = c3;
    }
    __syncthreads();        // qe ready; G (emb_k) free

    // ---------------- phase B (R6 structure, TJ=256): scores ----------------
    const int jbase = warp * 16;
    const int i_lo = gid, i_hi = gid + 8;
    const int pi_lo = posi[i_lo], pi_hi = posi[i_hi];
    const size_t row_lo = ((size_t)b * LL + (i0 + i_lo)) * LL;
    const size_t row_hi = ((size_t)b * LL + (i0 + i_hi)) * LL;

    for (int jt = 0; jt < LL / TJ; jt++) {
        {   // k tile [256][64] -> G stride 68, tf32 rna
            const float4* k4 = (const float4*)(gk + ((size_t)b * LL + jt * TJ) * DD);
            #pragma unroll
            for (int f = tid; f < TJ * (DD/4); f += NT) {
                int j = f >> 4, d4 = f & 15;
                *(float4*)(G + j * KSTR + d4 * 4) = tf32r4(k4[f]);
            }
        }
        __syncthreads();

        float c[2][4];
        #pragma unroll
        for (int t = 0; t < 2; t++)
            #pragma unroll
            for (int x = 0; x < 4; x++) c[t][x] = 0.f;

        #pragma unroll
        for (int ks = 0; ks < 8; ks++) {
            #pragma unroll
            for (int t = 0; t < 2; t++) {
                const float* kb = G + (jbase + t * 8 + gid) * KSTR + ks * 8 + tid4;
                unsigned b0 = __float_as_uint(kb[0]);
                unsigned b1 = __float_as_uint(kb[4]);
                MMA_TF32(c[t][0], c[t][1], c[t][2], c[t][3],
                         af[ks][0], af[ks][1], af[ks][2], af[ks][3], b0, b1);
            }
        }

        #pragma unroll
        for (int t = 0; t < 2; t++) {
            int jg0 = jt * TJ + jbase + t * 8 + tid4 * 2;
            float2 w_lo = *(const float2*)(gw + row_lo + jg0);
            float2 w_hi = *(const float2*)(gw + row_hi + jg0);
            uchar2 m_lo = *(const uchar2*)(gmask + row_lo + jg0);
            uchar2 m_hi = *(const uchar2*)(gmask + row_hi + jg0);
            int pj0 = posa[jg0], pj1 = posa[jg0 + 1];
            int d00 = max(-64, min(64, pj0 - pi_lo)) + 64;
            int d01 = max(-64, min(64, pj1 - pi_lo)) + 64;
            int d10 = max(-64, min(64, pj0 - pi_hi)) + 64;
            int d11 = max(-64, min(64, pj1 - pi_hi)) + 64;
            float s00 = (c[t][0] + av_s[i_lo * AVSTR + d00] + w_lo.x) * 0.125f;
            float s01 = (c[t][1] + av_s[i_lo * AVSTR + d01] + w_lo.y) * 0.125f;
            float s10 = (c[t][2] + av_s[i_hi * AVSTR + d10] + w_hi.x) * 0.125f;
            float s11 = (c[t][3] + av_s[i_hi * AVSTR + d11] + w_hi.y) * 0.125f;
            if (m_lo.x) s00 = -INFINITY;
            if (m_lo.y) s01 = -INFINITY;
            if (m_hi.x) s10 = -INFINITY;
            if (m_hi.y) s11 = -INFINITY;
            *(float2*)(p_s + i_lo * PSTR + jg0) = make_float2(s00, s01);
            *(float2*)(p_s + i_hi * PSTR + jg0) = make_float2(s10, s11);
        }
        __syncthreads();
    }

    // ---------------- phase C: softmax + p write + av scatter -> g_av ----------------
    {
        const int i = warp;
        float* row = p_s + i * PSTR;
        float r[32];
        #pragma unroll
        for (int c = 0; c < 32; c++) r[c] = row[lane + 32*c];

        float m = -INFINITY;
        #pragma unroll
        for (int c = 0; c < 32; c++) m = fmaxf(m, r[c]);
        #pragma unroll
        for (int o = 16; o > 0; o >>= 1) m = fmaxf(m, __shfl_xor_sync(FULL, m, o));

        float sum = 0.f;
        #pragma unroll
        for (int c = 0; c < 32; c++) {
            r[c] = __expf(r[c] - m);
            sum += r[c];
        }
        #pragma unroll
        for (int o = 16; o > 0; o >>= 1) sum += __shfl_xor_sync(FULL, sum, o);
        float inv = 1.0f / sum;

        // fixed-point scatter, 2 banks per bucket (exact -> deterministic)
        unsigned long long* a64 = (unsigned long long*)G + (size_t)i * 264;
        #pragma unroll
        for (int c = 0; c < 9; c++) {
            int idx = lane + 32*c;
            if (idx < 264) a64[idx] = 0ull;
        }
        __syncwarp();

        const int pi = posi[i];
        const int bank = lane & 1;
        const size_t prow = ((size_t)b * LL + (i0 + i)) * LL;
        #pragma unroll
        for (int c = 0; c < 32; c++) {
            int j = lane + 32*c;
            float pv = r[c] * inv;
            pdst[prow + j] = pv;                    // exact p out
            int diff = posa[j] - pi;
            diff = max(-64, min(64, diff));
            atomicAdd(a64 + (diff + 64) * 2 + bank,
                      (unsigned long long)(pv * FIX_SCALE));
        }
        __syncwarp();

        // write av row (exact), zero-padded to 192 cols
        float* avout = g_av + ((size_t)b * LL + i0 + i) * AVG;
        #pragma unroll
        for (int c = 0; c < 6; c++) {
            int idx = lane + 32*c;                  // 0..191
            float val = 0.f;
            if (idx < RR)
                val = __ull2float_rn(a64[idx*2] + a64[idx*2+1]) * FIX_INV;
            avout[idx] = val;
        }
    }
}

// ===================== K2: out = p @ v + av @ emb_v =====================
#define NT2 256

extern "C" __global__ void __launch_bounds__(NT2, 4)
pv_kernel(const float* __restrict__ gp_in, const float* __restrict__ gv,
          const float* __restrict__ gev, float* __restrict__ gout)
{
    __shared__ float ps2[64 * 68];
    __shared__ float vs2[64 * 72];

    const int b    = blockIdx.y;
    const int i0b  = blockIdx.x * 64;
    const int tid  = threadIdx.x;
    const int lane = tid & 31;
    const int warp = tid >> 5;          // 0..7
    const int gid  = lane >> 2;
    const int tid4 = lane & 3;
    const int mrow = (warp & 3) * 16;
    const int ncol = (warp >> 2) * 32;

    const float* psrc = gp_in ? gp_in : g_p_scratch;

    float acc[4][4];
    #pragma unroll
    for (int nt = 0; nt < 4; nt++)
        #pragma unroll
        for (int x = 0; x < 4; x++) acc[nt][x] = 0.f;

    for (int t = 0; t < 19; t++) {
        if (t < 16) {
            // A: p[i0b..+63][t*64..+63]   B: v[t*64..+63][0..63]
            const float4* pa = (const float4*)(psrc + ((size_t)b * LL + i0b) * LL + t * 64);
            const float4* va = (const float4*)(gv + ((size_t)b * LL + t * 64) * DD);
            #pragma unroll
            for (int s = 0; s < 4; s++) {
                int f = tid + s * NT2;
                int r = f >> 4, c4 = f & 15;
                *(float4*)(ps2 + r * 68 + c4 * 4) = tf32r4(pa[r * 256 + c4]);
                *(float4*)(vs2 + r * 72 + c4 * 4) = tf32r4(va[f]);
            }
        } else {
            // A: av[i0b..+63][kc*64..+63]  B: emb_v rows kc*64..+63 (0 beyond RR)
            int kc = t - 16;
            const float4* aa = (const float4*)(g_av + ((size_t)b * LL + i0b) * AVG + kc * 64);
            #pragma unroll
            for (int s = 0; s < 4; s++) {
                int f = tid + s * NT2;
                int r = f >> 4, c4 = f & 15;
                *(float4*)(ps2 + r * 68 + c4 * 4) = tf32r4(aa[r * (AVG/4) + c4]);
                int kr = kc * 64 + r;
                float4 ev = make_float4(0.f, 0.f, 0.f, 0.f);
                if (kr < RR)
                    ev = tf32r4(((const float4*)(gev + kr * DD))[c4]);
                *(float4*)(vs2 + r * 72 + c4 * 4) = ev;
            }
        }
        __syncthreads();

        #pragma unroll
        for (int ks = 0; ks < 8; ks++) {
            unsigned a0 = __float_as_uint(ps2[(mrow + gid)     * 68 + ks * 8 + tid4    ]);
            unsigned a1 = __float_as_uint(ps2[(mrow + gid + 8) * 68 + ks * 8 + tid4    ]);
            unsigned a2 = __float_as_uint(ps2[(mrow + gid)     * 68 + ks * 8 + tid4 + 4]);
            unsigned a3 = __float_as_uint(ps2[(mrow + gid + 8) * 68 + ks * 8 + tid4 + 4]);
            #pragma unroll
            for (int nt = 0; nt < 4; nt++) {
                unsigned b0 = __float_as_uint(vs2[(ks * 8 + tid4)     * 72 + ncol + nt * 8 + gid]);
                unsigned b1 = __float_as_uint(vs2[(ks * 8 + tid4 + 4) * 72 + ncol + nt * 8 + gid]);
                MMA_TF32(acc[nt][0], acc[nt][1], acc[nt][2], acc[nt][3],
                         a0, a1, a2, a3, b0, b1);
            }
        }
        __syncthreads();
    }

    #pragma unroll
    for (int nt = 0; nt < 4; nt++) {
        int col = ncol + nt * 8 + tid4 * 2;
        *(float2*)(gout + ((size_t)b * LL + i0b + mrow + gid)     * DD + col) =
            make_float2(acc[nt][0], acc[nt][1]);
        *(float2*)(gout + ((size_t)b * LL + i0b + mrow + gid + 8) * DD + col) =
            make_float2(acc[nt][2], acc[nt][3]);
    }
}

extern "C" void kernel_launch(void* const* d_in, const int* in_sizes, int n_in,
                              void* d_out, int out_size)
{
    const float* q   = (const float*)d_in[0];
    const float* k   = (const float*)d_in[1];
    const float* v   = (const float*)d_in[2];
    const float* w   = (const float*)d_in[3];
    const float* ek  = (const float*)d_in[4];
    const float* ev  = (const float*)d_in[5];
    const int*   pos = (const int*)d_in[6];
    const unsigned char* mask = (const unsigned char*)d_in[7];

    const long OUT_N = (long)BNH * LL * DD;   // 2,097,152
    const long P_N   = (long)BNH * LL * LL;   // 33,554,432

    float* outp = nullptr;
    float* pp   = nullptr;
    if ((long)out_size == OUT_N) {
        outp = (float*)d_out;
    } else if ((long)out_size == P_N) {
        pp = (float*)d_out;
    } else {
        outp = (float*)d_out;
        pp   = (float*)d_out + OUT_N;
    }

    cudaFuncSetAttribute(attn_scores_kernel,
                         cudaFuncAttributeMaxDynamicSharedMemorySize, K1_BYTES);
    dim3 grid1(LL / TI, BNH);
    attn_scores_kernel<<<grid1, NT, K1_BYTES>>>(q, k, w, ek, pos, mask, pp);

    if (outp) {
        dim3 grid2(LL / 64, BNH);
        pv_kernel<<<grid2, NT2>>>(pp, v, ev, outp);
    }
}